// round 14
// baseline (speedup 1.0000x reference)
#include <cuda_runtime.h>
#include <math.h>

#define T_LEN 2048
#define B_SZ  64
#define CIN   64
#define HID   128
#define G4    512
#define TT    64
#define NTILE (T_LEN/TT)   // 32 tiles per batch row

#define NT    256          // threads per block (both paths)
#define REGK  112          // w_hh columns register-resident per row
#define SMEMK 16           // remaining columns in shared memory (8 pairs)
#define NPAIR (SMEMK/2)

#define LSTM_SMEM_BYTES (NPAIR*256*16 + 2*HID*4)            // 33792
#define GX_SMEM_BYTES   ((CIN*TT + CIN*68 + 5*CIN)*4)       // 35072
#define FUSED_SMEM      (GX_SMEM_BYTES > LSTM_SMEM_BYTES ? GX_SMEM_BYTES : LSTM_SMEM_BYTES)

// packed fp32x2 helpers (sm_103a). "f" = .f32 reg, "l" = .b64 reg.
#define FMA2(d, a, b, c) \
    asm("fma.rn.f32x2 %0, %1, %2, %3;" : "=l"(d) : "l"(a), "l"(b), "l"(c))
#define PACK2(out, lo, hi) \
    asm("mov.b64 %0, {%1, %2};" : "=l"(out) : "f"(lo), "f"(hi))
#define UNPACK2(lo, hi, in) \
    asm("mov.b64 {%0, %1}, %2;" : "=f"(lo), "=f"(hi) : "l"(in))

__device__ float g_gx [(size_t)B_SZ * T_LEN * G4];   // [b][t][g]
__device__ float g_WcT[CIN * G4];                    // [k][g]
__device__ float g_bc [G4];
__device__ int   g_flag[B_SZ * NTILE];               // [b][tile] ready flags

// ---------------------------------------------------------------------------
// Stage 0: fold pointwise conv into LSTM input projection; zero tile flags.
// ---------------------------------------------------------------------------
__global__ __launch_bounds__(512, 1)
void prep_kernel(const float* __restrict__ pw_w,
                 const float* __restrict__ pw_b,
                 const float* __restrict__ w_ih,
                 const float* __restrict__ b_ih,
                 const float* __restrict__ b_hh)
{
    __shared__ float wt[8 * HID];
    if (blockIdx.x < 4)
        g_flag[blockIdx.x * 512 + threadIdx.x] = 0;    // 4*512 == B_SZ*NTILE

    const int g0 = blockIdx.x * 8;
    for (int i = threadIdx.x; i < 8 * HID; i += 512)
        wt[i] = w_ih[(size_t)g0 * HID + i];
    __syncthreads();

    const int gi = threadIdx.x >> 6;   // 0..7
    const int k  = threadIdx.x & 63;   // 0..63
    const int g  = g0 + gi;

    float s = 0.f;
    #pragma unroll 16
    for (int o = 0; o < HID; ++o)
        s = fmaf(wt[gi*HID + o], pw_w[o*CIN + k], s);
    g_WcT[k*G4 + g] = s;

    if (k == 0) {
        float sb = b_ih[g] + b_hh[g];
        #pragma unroll 16
        for (int o = 0; o < HID; ++o)
            sb = fmaf(wt[gi*HID + o], pw_b[o], sb);
        g_bc[g] = sb;
    }
}

// ---------------------------------------------------------------------------
// Activation helpers
// ---------------------------------------------------------------------------
__device__ __forceinline__ float tanh_ap(float x) {
    float y;
    asm("tanh.approx.f32 %0, %1;" : "=f"(y) : "f"(x));
    return y;
}
__device__ __forceinline__ float sigmoid_ap(float x) {
    return fmaf(tanh_ap(0.5f * x), 0.5f, 0.5f);
}
__device__ __forceinline__ void wait_flag(const int* fp) {
    int v;
    do {
        asm volatile("ld.acquire.gpu.global.b32 %0, [%1];"
                     : "=r"(v) : "l"(fp) : "memory");
    } while (v == 0);
}

// ---------------------------------------------------------------------------
// gx producer path: one block per (tile, batch). 256 threads; thread owns
// gate rows g=tid and g+256 over a 64-wide t-tile.
// u = relu(BN(dwconv(x))) + x  fused with  gx = Wc @ u + bc.
// ---------------------------------------------------------------------------
__device__ void gx_path(char* smraw, int e,
                        const float* __restrict__ x,
                        const float* __restrict__ dw_w, const float* __restrict__ dw_b,
                        const float* __restrict__ bn_g, const float* __restrict__ bn_b,
                        const float* __restrict__ bn_m, const float* __restrict__ bn_v)
{
    float* us = (float*)smraw;            // [CIN][TT]
    float* xs = us + CIN*TT;              // [CIN][68] (66 used)
    float* ca = xs + CIN*68;
    float* cd  = ca + CIN;
    float* cw0 = cd + CIN;
    float* cw1 = cw0 + CIN;
    float* cw2 = cw1 + CIN;

    const int tid = threadIdx.x;
    const int b   = e & 63;               // low bits = batch -> tiles produced t-ascending
    const int kt  = e >> 6;               // tile index
    const int t0  = kt * TT;

    if (tid < CIN) {
        int c = tid;
        float inv = bn_g[c] * rsqrtf(bn_v[c] + 1e-5f);
        ca[c]  = inv;
        cd[c]  = (dw_b[c] - bn_m[c]) * inv + bn_b[c];
        cw0[c] = dw_w[c*3 + 0];
        cw1[c] = dw_w[c*3 + 1];
        cw2[c] = dw_w[c*3 + 2];
    }
    for (int idx = tid; idx < CIN * 66; idx += NT) {
        int c = idx / 66, i = idx % 66;
        int t = t0 - 1 + i;
        xs[c*68 + i] = (t >= 0 && t < T_LEN) ? x[((size_t)b*CIN + c)*T_LEN + t] : 0.f;
    }
    __syncthreads();

    for (int idx = tid; idx < CIN * TT; idx += NT) {
        int c = idx >> 6, tt = idx & 63;
        const float* xr = xs + c*68 + tt;
        float conv = fmaf(cw0[c], xr[0], fmaf(cw1[c], xr[1], cw2[c]*xr[2]));
        float v = fmaf(conv, ca[c], cd[c]);
        us[c*TT + tt] = fmaxf(v, 0.f) + xr[1];
    }
    __syncthreads();

    const int g  = tid;
    const int g2 = tid + 256;
    unsigned long long accA[TT/2], accB[TT/2];
    {
        float bA = g_bc[g], bB = g_bc[g2];
        unsigned long long pA, pB;
        PACK2(pA, bA, bA);
        PACK2(pB, bB, bB);
        #pragma unroll
        for (int q = 0; q < TT/2; ++q) { accA[q] = pA; accB[q] = pB; }
    }
    #pragma unroll 2
    for (int k = 0; k < CIN; ++k) {
        float wa = g_WcT[k*G4 + g];
        float wb = g_WcT[k*G4 + g2];
        unsigned long long wpa, wpb;
        PACK2(wpa, wa, wa);
        PACK2(wpb, wb, wb);
        const ulonglong2* u2 = (const ulonglong2*)(us + (k << 6));
        #pragma unroll
        for (int q = 0; q < TT/4; ++q) {
            ulonglong2 uv = u2[q];
            FMA2(accA[2*q+0], wpa, uv.x, accA[2*q+0]);
            FMA2(accA[2*q+1], wpa, uv.y, accA[2*q+1]);
            FMA2(accB[2*q+0], wpb, uv.x, accB[2*q+0]);
            FMA2(accB[2*q+1], wpb, uv.y, accB[2*q+1]);
        }
    }
    float* outp = g_gx + ((size_t)(b*T_LEN + t0)) * G4;
    #pragma unroll
    for (int q = 0; q < TT/2; ++q) {
        float lo, hi;
        UNPACK2(lo, hi, accA[q]);
        outp[(size_t)(2*q+0) * G4 + g] = lo;
        outp[(size_t)(2*q+1) * G4 + g] = hi;
        UNPACK2(lo, hi, accB[q]);
        outp[(size_t)(2*q+0) * G4 + g2] = lo;
        outp[(size_t)(2*q+1) * G4 + g2] = hi;
    }

    __threadfence();
    __syncthreads();
    if (tid == 0)
        asm volatile("st.release.gpu.global.b32 [%0], %1;"
                     :: "l"(&g_flag[b*NTILE + kt]), "r"(1) : "memory");
}

// ---------------------------------------------------------------------------
// LSTM consumer path: one block per batch row, 256 threads. (R9/R13 loop —
// at the register ceiling; waits on producer flags at tile boundaries.)
// ---------------------------------------------------------------------------
__device__ void lstm_path(char* smraw, int b,
                          const float* __restrict__ w_hh, float* __restrict__ out)
{
    ulonglong2* ws4  = (ulonglong2*)smraw;                 // [NPAIR][256]
    float*      hbuf = (float*)(smraw + NPAIR*256*16);     // [2][128]

    const int t    = threadIdx.x;
    const int cell = t >> 1;
    const int odd  = t & 1;
    const int r0   = cell + (odd ? 128 : 0);        // gate i or f
    const int r1   = cell + 256 + (odd ? 128 : 0);  // gate g or o

    // register-resident weight pairs (cols 0..REGK-1) for both rows
    unsigned long long wA[REGK/2], wB[REGK/2];
    {
        const ulonglong2* pA = (const ulonglong2*)(w_hh + (size_t)r0 * HID);
        const ulonglong2* pB = (const ulonglong2*)(w_hh + (size_t)r1 * HID);
        #pragma unroll
        for (int q = 0; q < REGK/4; ++q) {
            ulonglong2 vA = pA[q]; wA[2*q] = vA.x; wA[2*q+1] = vA.y;
            ulonglong2 vB = pB[q]; wB[2*q] = vB.x; wB[2*q+1] = vB.y;
        }
    }
    // smem weights: cols REGK..127 as f32x2 pairs, both rows per element
    #pragma unroll
    for (int j = 0; j < NPAIR; ++j) {
        unsigned long long pa =
            *(const unsigned long long*)(w_hh + (size_t)r0*HID + REGK + 2*j);
        unsigned long long pb =
            *(const unsigned long long*)(w_hh + (size_t)r1*HID + REGK + 2*j);
        ws4[(j << 8) + t] = make_ulonglong2(pa, pb);
    }
    hbuf[t] = 0.f;     // t covers both 128-wide buffers (NT == 256)

    float c_state = 0.f;
    const float* gxA = g_gx + (size_t)b * T_LEN * G4 + r0;
    const float* gxB = g_gx + (size_t)b * T_LEN * G4 + r1;

    wait_flag(&g_flag[b*NTILE + 0]);                 // tile 0 ready
    float gxA_n = gxA[0], gxB_n = gxB[0];
    float* outp = out + (size_t)b * HID * T_LEN + (size_t)cell * T_LEN;
    __syncthreads();

    int p = 0;
    for (int step = 0; step < T_LEN; ++step) {
        if ((step & 63) == 0) {                      // cover prefetch into next tile
            int nt = (step >> 6) + 1;
            if (nt < NTILE) wait_flag(&g_flag[b*NTILE + nt]);
        }
        float accA = gxA_n, accB = gxB_n;
        if (step + 1 < T_LEN) {
            gxA_n = gxA[(size_t)(step+1) * G4];
            gxB_n = gxB[(size_t)(step+1) * G4];
        }

        unsigned long long a2, b2;
        PACK2(a2, accA, 0.f);
        PACK2(b2, accB, 0.f);

        const ulonglong2*         h2 = (const ulonglong2*)(hbuf + p*HID);
        const unsigned long long* h1 = (const unsigned long long*)(hbuf + p*HID);
        #pragma unroll
        for (int i = 0; i < REGK/4; ++i) {            // cols 0..REGK-1
            ulonglong2 hv = h2[i];                    // broadcast LDS.128
            FMA2(a2, wA[2*i+0], hv.x, a2);
            FMA2(b2, wB[2*i+0], hv.x, b2);
            FMA2(a2, wA[2*i+1], hv.y, a2);
            FMA2(b2, wB[2*i+1], hv.y, b2);
        }
        #pragma unroll
        for (int j = 0; j < NPAIR; ++j) {             // cols REGK..127
            unsigned long long hv = h1[REGK/2 + j];   // broadcast LDS.64
            ulonglong2 wv = ws4[(j << 8) + t];        // LDS.128
            FMA2(a2, wv.x, hv, a2);
            FMA2(b2, wv.y, hv, b2);
        }
        float gA, gB;
        {
            float l0, h0, l1, hh1;
            UNPACK2(l0, h0, a2);
            UNPACK2(l1, hh1, b2);
            gA = l0 + h0;
            gB = l1 + hh1;
        }

        // even: sA = sigma(i), vB = tanh(g); odd: sA = sigma(f), vB = sigma(o)
        float sA = sigmoid_ap(gA);
        float tB = tanh_ap(odd ? 0.5f * gB : gB);
        float vB = odd ? fmaf(tB, 0.5f, 0.5f) : tB;
        float ig = sA * vB;                           // even lanes: sigma(i)*tanh(g)
        float ig_s = __shfl_up_sync(0xFFFFFFFFu, ig, 1);
        if (odd) {
            c_state = fmaf(sA, c_state, ig_s);
            float h = vB * tanh_ap(c_state);
            hbuf[(p ^ 1)*HID + cell] = h;             // write buffer, no race
            outp[step] = h;
        }
        __syncthreads();                              // publish h for step+1
        p ^= 1;
    }
}

// ---------------------------------------------------------------------------
// Fused kernel: bid 0..63 = lstm consumers (wave-1 resident); bid >= 64 =
// gx producers backfilled on the remaining SMs.
// ---------------------------------------------------------------------------
__global__ __launch_bounds__(NT, 1)
void fused_kernel(const float* __restrict__ w_hh, float* __restrict__ out,
                  const float* __restrict__ x,
                  const float* __restrict__ dw_w, const float* __restrict__ dw_b,
                  const float* __restrict__ bn_g, const float* __restrict__ bn_b,
                  const float* __restrict__ bn_m, const float* __restrict__ bn_v)
{
    extern __shared__ __align__(16) char smraw[];
    if (blockIdx.x < B_SZ)
        lstm_path(smraw, blockIdx.x, w_hh, out);
    else
        gx_path(smraw, blockIdx.x - B_SZ, x, dw_w, dw_b, bn_g, bn_b, bn_m, bn_v);
}

// ---------------------------------------------------------------------------
extern "C" void kernel_launch(void* const* d_in, const int* in_sizes, int n_in,
                              void* d_out, int out_size)
{
    (void)in_sizes; (void)n_in; (void)out_size;
    const float* x     = (const float*)d_in[0];
    const float* dw_w  = (const float*)d_in[1];
    const float* dw_b  = (const float*)d_in[2];
    const float* bn_g  = (const float*)d_in[3];
    const float* bn_b  = (const float*)d_in[4];
    const float* bn_m  = (const float*)d_in[5];
    const float* bn_v  = (const float*)d_in[6];
    const float* pw_w  = (const float*)d_in[7];
    const float* pw_b  = (const float*)d_in[8];
    const float* w_ih  = (const float*)d_in[9];
    const float* w_hh  = (const float*)d_in[10];
    const float* b_ih  = (const float*)d_in[11];
    const float* b_hh  = (const float*)d_in[12];
    float* out = (float*)d_out;

    cudaFuncSetAttribute(fused_kernel,
                         cudaFuncAttributeMaxDynamicSharedMemorySize, FUSED_SMEM);

    prep_kernel<<<64, 512>>>(pw_w, pw_b, w_ih, b_ih, b_hh);
    fused_kernel<<<B_SZ + B_SZ*NTILE, NT, FUSED_SMEM>>>(
        w_hh, out, x, dw_w, dw_b, bn_g, bn_b, bn_m, bn_v);
}

// round 15
// speedup vs baseline: 1.6215x; 1.6215x over previous
#include <cuda_runtime.h>
#include <math.h>

#define T_LEN 2048
#define B_SZ  64
#define CIN   64
#define HID   128
#define G4    512
#define TT    64
#define NTILE (T_LEN/TT)   // 32 tiles per batch row

#define NT    256          // threads per block (both paths)
#define REGK  112          // w_hh columns register-resident per row
#define SMEMK 16           // remaining columns in shared memory (8 pairs)
#define NPAIR (SMEMK/2)

#define LSTM_SMEM_BYTES (NPAIR*256*16 + 2*HID*4)            // 33792
#define GX_SMEM_BYTES   ((CIN*TT + CIN*68 + 5*CIN)*4)       // 35072
#define FUSED_SMEM      (GX_SMEM_BYTES > LSTM_SMEM_BYTES ? GX_SMEM_BYTES : LSTM_SMEM_BYTES)

// packed fp32x2 helpers (sm_103a). "f" = .f32 reg, "l" = .b64 reg.
#define FMA2(d, a, b, c) \
    asm("fma.rn.f32x2 %0, %1, %2, %3;" : "=l"(d) : "l"(a), "l"(b), "l"(c))
#define PACK2(out, lo, hi) \
    asm("mov.b64 %0, {%1, %2};" : "=l"(out) : "f"(lo), "f"(hi))
#define UNPACK2(lo, hi, in) \
    asm("mov.b64 {%0, %1}, %2;" : "=f"(lo), "=f"(hi) : "l"(in))

__device__ float g_gx [(size_t)B_SZ * T_LEN * G4];   // [b][t][g]
__device__ float g_WcT[CIN * G4];                    // [k][g]
__device__ float g_bc [G4];
__device__ int   g_flag[B_SZ * NTILE];               // [b][tile] ready flags

// ---------------------------------------------------------------------------
// Stage 0: fold pointwise conv into LSTM input projection; zero tile flags.
// ---------------------------------------------------------------------------
__global__ __launch_bounds__(512, 1)
void prep_kernel(const float* __restrict__ pw_w,
                 const float* __restrict__ pw_b,
                 const float* __restrict__ w_ih,
                 const float* __restrict__ b_ih,
                 const float* __restrict__ b_hh)
{
    __shared__ float wt[8 * HID];
    if (blockIdx.x < 4)
        g_flag[blockIdx.x * 512 + threadIdx.x] = 0;    // 4*512 == B_SZ*NTILE

    const int g0 = blockIdx.x * 8;
    for (int i = threadIdx.x; i < 8 * HID; i += 512)
        wt[i] = w_ih[(size_t)g0 * HID + i];
    __syncthreads();

    const int gi = threadIdx.x >> 6;   // 0..7
    const int k  = threadIdx.x & 63;   // 0..63
    const int g  = g0 + gi;

    float s = 0.f;
    #pragma unroll 16
    for (int o = 0; o < HID; ++o)
        s = fmaf(wt[gi*HID + o], pw_w[o*CIN + k], s);
    g_WcT[k*G4 + g] = s;

    if (k == 0) {
        float sb = b_ih[g] + b_hh[g];
        #pragma unroll 16
        for (int o = 0; o < HID; ++o)
            sb = fmaf(wt[gi*HID + o], pw_b[o], sb);
        g_bc[g] = sb;
    }
}

// ---------------------------------------------------------------------------
// Activation helpers
// ---------------------------------------------------------------------------
__device__ __forceinline__ float tanh_ap(float x) {
    float y;
    asm("tanh.approx.f32 %0, %1;" : "=f"(y) : "f"(x));
    return y;
}
__device__ __forceinline__ float sigmoid_ap(float x) {
    return fmaf(tanh_ap(0.5f * x), 0.5f, 0.5f);
}
__device__ __forceinline__ void wait_flag(const int* fp) {
    int v;
    do {
        asm volatile("ld.acquire.gpu.global.b32 %0, [%1];"
                     : "=r"(v) : "l"(fp) : "memory");
    } while (v == 0);
}

// ---------------------------------------------------------------------------
// gx producer path: one block per (tile, batch). 256 threads; thread owns
// gate rows g=tid and g+256. t-tile processed in two 32-wide halves to keep
// accumulator register demand (64 regs) well below the lstm path's.
// ---------------------------------------------------------------------------
__device__ void gx_path(char* smraw, int e,
                        const float* __restrict__ x,
                        const float* __restrict__ dw_w, const float* __restrict__ dw_b,
                        const float* __restrict__ bn_g, const float* __restrict__ bn_b,
                        const float* __restrict__ bn_m, const float* __restrict__ bn_v)
{
    float* us = (float*)smraw;            // [CIN][TT]
    float* xs = us + CIN*TT;              // [CIN][68] (66 used)
    float* ca = xs + CIN*68;
    float* cd  = ca + CIN;
    float* cw0 = cd + CIN;
    float* cw1 = cw0 + CIN;
    float* cw2 = cw1 + CIN;

    const int tid = threadIdx.x;
    const int b   = e & 63;               // low bits = batch -> tiles produced t-ascending
    const int kt  = e >> 6;               // tile index
    const int t0  = kt * TT;

    if (tid < CIN) {
        int c = tid;
        float inv = bn_g[c] * rsqrtf(bn_v[c] + 1e-5f);
        ca[c]  = inv;
        cd[c]  = (dw_b[c] - bn_m[c]) * inv + bn_b[c];
        cw0[c] = dw_w[c*3 + 0];
        cw1[c] = dw_w[c*3 + 1];
        cw2[c] = dw_w[c*3 + 2];
    }
    for (int idx = tid; idx < CIN * 66; idx += NT) {
        int c = idx / 66, i = idx % 66;
        int t = t0 - 1 + i;
        xs[c*68 + i] = (t >= 0 && t < T_LEN) ? x[((size_t)b*CIN + c)*T_LEN + t] : 0.f;
    }
    __syncthreads();

    for (int idx = tid; idx < CIN * TT; idx += NT) {
        int c = idx >> 6, tt = idx & 63;
        const float* xr = xs + c*68 + tt;
        float conv = fmaf(cw0[c], xr[0], fmaf(cw1[c], xr[1], cw2[c]*xr[2]));
        float v = fmaf(conv, ca[c], cd[c]);
        us[c*TT + tt] = fmaxf(v, 0.f) + xr[1];
    }
    __syncthreads();

    const int g  = tid;
    const int g2 = tid + 256;
    float* outp = g_gx + ((size_t)(b*T_LEN + t0)) * G4;

    #pragma unroll
    for (int half = 0; half < 2; ++half) {            // 32 t-values per pass
        unsigned long long accA[16], accB[16];
        {
            float bA = g_bc[g], bB = g_bc[g2];
            unsigned long long pA, pB;
            PACK2(pA, bA, bA);
            PACK2(pB, bB, bB);
            #pragma unroll
            for (int q = 0; q < 16; ++q) { accA[q] = pA; accB[q] = pB; }
        }
        #pragma unroll 2
        for (int k = 0; k < CIN; ++k) {
            float wa = g_WcT[k*G4 + g];
            float wb = g_WcT[k*G4 + g2];
            unsigned long long wpa, wpb;
            PACK2(wpa, wa, wa);
            PACK2(wpb, wb, wb);
            const ulonglong2* u2 =
                (const ulonglong2*)(us + (k << 6) + half*32);
            #pragma unroll
            for (int q = 0; q < 8; ++q) {
                ulonglong2 uv = u2[q];
                FMA2(accA[2*q+0], wpa, uv.x, accA[2*q+0]);
                FMA2(accA[2*q+1], wpa, uv.y, accA[2*q+1]);
                FMA2(accB[2*q+0], wpb, uv.x, accB[2*q+0]);
                FMA2(accB[2*q+1], wpb, uv.y, accB[2*q+1]);
            }
        }
        float* op = outp + (size_t)(half*32) * G4;
        #pragma unroll
        for (int q = 0; q < 16; ++q) {
            float lo, hi;
            UNPACK2(lo, hi, accA[q]);
            op[(size_t)(2*q+0) * G4 + g] = lo;
            op[(size_t)(2*q+1) * G4 + g] = hi;
            UNPACK2(lo, hi, accB[q]);
            op[(size_t)(2*q+0) * G4 + g2] = lo;
            op[(size_t)(2*q+1) * G4 + g2] = hi;
        }
    }

    __threadfence();
    __syncthreads();
    if (tid == 0)
        asm volatile("st.release.gpu.global.b32 [%0], %1;"
                     :: "l"(&g_flag[b*NTILE + kt]), "r"(1) : "memory");
}

// ---------------------------------------------------------------------------
// LSTM consumer path: one block per batch row, 256 threads. R13 inner loop
// verbatim; producer-flag waits hoisted to tile boundaries (outer loop) so
// no extra registers live inside the matvec loop.
// ---------------------------------------------------------------------------
__device__ void lstm_path(char* smraw, int b,
                          const float* __restrict__ w_hh, float* __restrict__ out)
{
    ulonglong2* ws4  = (ulonglong2*)smraw;                 // [NPAIR][256]
    float*      hbuf = (float*)(smraw + NPAIR*256*16);     // [2][128]

    const int t    = threadIdx.x;
    const int cell = t >> 1;
    const int odd  = t & 1;
    const int r0   = cell + (odd ? 128 : 0);        // gate i or f
    const int r1   = cell + 256 + (odd ? 128 : 0);  // gate g or o

    // register-resident weight pairs (cols 0..REGK-1) for both rows
    unsigned long long wA[REGK/2], wB[REGK/2];
    {
        const ulonglong2* pA = (const ulonglong2*)(w_hh + (size_t)r0 * HID);
        const ulonglong2* pB = (const ulonglong2*)(w_hh + (size_t)r1 * HID);
        #pragma unroll
        for (int q = 0; q < REGK/4; ++q) {
            ulonglong2 vA = pA[q]; wA[2*q] = vA.x; wA[2*q+1] = vA.y;
            ulonglong2 vB = pB[q]; wB[2*q] = vB.x; wB[2*q+1] = vB.y;
        }
    }
    // smem weights: cols REGK..127 as f32x2 pairs, both rows per element
    #pragma unroll
    for (int j = 0; j < NPAIR; ++j) {
        unsigned long long pa =
            *(const unsigned long long*)(w_hh + (size_t)r0*HID + REGK + 2*j);
        unsigned long long pb =
            *(const unsigned long long*)(w_hh + (size_t)r1*HID + REGK + 2*j);
        ws4[(j << 8) + t] = make_ulonglong2(pa, pb);
    }
    hbuf[t] = 0.f;     // t covers both 128-wide buffers (NT == 256)

    float c_state = 0.f;
    const float* gxA = g_gx + (size_t)b * T_LEN * G4 + r0;
    const float* gxB = g_gx + (size_t)b * T_LEN * G4 + r1;
    const int* flagb = &g_flag[b*NTILE];

    wait_flag(flagb);                                // tile 0 ready
    float gxA_n = gxA[0], gxB_n = gxB[0];
    float* outp = out + (size_t)b * HID * T_LEN + (size_t)cell * T_LEN;
    __syncthreads();

    int p = 0;
    for (int kt = 0; kt < NTILE; ++kt) {
        // tile kt is ready (waited at tile kt-1 / before loop). Wait for
        // kt+1 here so the one-step prefetch into it is covered.
        if (kt + 1 < NTILE) wait_flag(flagb + kt + 1);

        const int stepEnd = (kt + 1) * TT;
        for (int step = kt * TT; step < stepEnd; ++step) {
            float accA = gxA_n, accB = gxB_n;
            if (step + 1 < T_LEN) {
                gxA_n = gxA[(size_t)(step+1) * G4];
                gxB_n = gxB[(size_t)(step+1) * G4];
            }

            unsigned long long a2, b2;
            PACK2(a2, accA, 0.f);
            PACK2(b2, accB, 0.f);

            const ulonglong2*         h2 = (const ulonglong2*)(hbuf + p*HID);
            const unsigned long long* h1 = (const unsigned long long*)(hbuf + p*HID);
            #pragma unroll
            for (int i = 0; i < REGK/4; ++i) {            // cols 0..REGK-1
                ulonglong2 hv = h2[i];                    // broadcast LDS.128
                FMA2(a2, wA[2*i+0], hv.x, a2);
                FMA2(b2, wB[2*i+0], hv.x, b2);
                FMA2(a2, wA[2*i+1], hv.y, a2);
                FMA2(b2, wB[2*i+1], hv.y, b2);
            }
            #pragma unroll
            for (int j = 0; j < NPAIR; ++j) {             // cols REGK..127
                unsigned long long hv = h1[REGK/2 + j];   // broadcast LDS.64
                ulonglong2 wv = ws4[(j << 8) + t];        // LDS.128
                FMA2(a2, wv.x, hv, a2);
                FMA2(b2, wv.y, hv, b2);
            }
            float gA, gB;
            {
                float l0, h0, l1, hh1;
                UNPACK2(l0, h0, a2);
                UNPACK2(l1, hh1, b2);
                gA = l0 + h0;
                gB = l1 + hh1;
            }

            // even: sA = sigma(i), vB = tanh(g); odd: sA = sigma(f), vB = sigma(o)
            float sA = sigmoid_ap(gA);
            float tB = tanh_ap(odd ? 0.5f * gB : gB);
            float vB = odd ? fmaf(tB, 0.5f, 0.5f) : tB;
            float ig = sA * vB;                       // even: sigma(i)*tanh(g)
            float ig_s = __shfl_up_sync(0xFFFFFFFFu, ig, 1);
            if (odd) {
                c_state = fmaf(sA, c_state, ig_s);
                float h = vB * tanh_ap(c_state);
                hbuf[(p ^ 1)*HID + cell] = h;         // write buffer, no race
                outp[step] = h;
            }
            __syncthreads();                          // publish h for step+1
            p ^= 1;
        }
    }
}

// ---------------------------------------------------------------------------
// Fused kernel: bid 0..63 = lstm consumers (wave-1 resident); bid >= 64 =
// gx producers backfilled on the remaining SMs.
// ---------------------------------------------------------------------------
__global__ __launch_bounds__(NT, 1)
void fused_kernel(const float* __restrict__ w_hh, float* __restrict__ out,
                  const float* __restrict__ x,
                  const float* __restrict__ dw_w, const float* __restrict__ dw_b,
                  const float* __restrict__ bn_g, const float* __restrict__ bn_b,
                  const float* __restrict__ bn_m, const float* __restrict__ bn_v)
{
    extern __shared__ __align__(16) char smraw[];
    if (blockIdx.x < B_SZ)
        lstm_path(smraw, blockIdx.x, w_hh, out);
    else
        gx_path(smraw, blockIdx.x - B_SZ, x, dw_w, dw_b, bn_g, bn_b, bn_m, bn_v);
}

// ---------------------------------------------------------------------------
extern "C" void kernel_launch(void* const* d_in, const int* in_sizes, int n_in,
                              void* d_out, int out_size)
{
    (void)in_sizes; (void)n_in; (void)out_size;
    const float* x     = (const float*)d_in[0];
    const float* dw_w  = (const float*)d_in[1];
    const float* dw_b  = (const float*)d_in[2];
    const float* bn_g  = (const float*)d_in[3];
    const float* bn_b  = (const float*)d_in[4];
    const float* bn_m  = (const float*)d_in[5];
    const float* bn_v  = (const float*)d_in[6];
    const float* pw_w  = (const float*)d_in[7];
    const float* pw_b  = (const float*)d_in[8];
    const float* w_ih  = (const float*)d_in[9];
    const float* w_hh  = (const float*)d_in[10];
    const float* b_ih  = (const float*)d_in[11];
    const float* b_hh  = (const float*)d_in[12];
    float* out = (float*)d_out;

    cudaFuncSetAttribute(fused_kernel,
                         cudaFuncAttributeMaxDynamicSharedMemorySize, FUSED_SMEM);

    prep_kernel<<<64, 512>>>(pw_w, pw_b, w_ih, b_ih, b_hh);
    fused_kernel<<<B_SZ + B_SZ*NTILE, NT, FUSED_SMEM>>>(
        w_hh, out, x, dw_w, dw_b, bn_g, bn_b, bn_m, bn_v);
}